// round 16
// baseline (speedup 1.0000x reference)
#include <cuda_runtime.h>
#include <math.h>

#define B_    32
#define T_    2
#define NT    196
#define D_    768
#define HEADS 12
#define HD    64
#define HT    14
#define WT    14
#define HS    96
#define WS    96
#define NS    (HS*WS)       // 9216
#define NK    (NS+1)        // 9217
#define SMH   (HS-HT+1)     // 83
#define SMW   (WS-WT+1)     // 83
#define NPW   16            // n-values per warp in attn
#define AWRP  4             // warps per attn block
#define DCH   8             // dim-chunks in proto grid
#define DPB   (D_/DCH)      // 96 threads per proto block

__device__ float    g_acc[T_][B_][D_];  // per-template masked sums (pre-division)
__device__ float    g_cnt[T_][B_];      // per-template counts
__device__ float    g_track[B_*NS];
__device__ float    g_blurh[B_*NS];     // fully blurred map
__device__ float    g_exp[B_*NS];       // exp(blur - max)
__device__ unsigned g_maxbits[B_];      // per-batch max as monotonic uint key

// float <-> monotonic unsigned key (exact; max over keys == max over floats)
__device__ __forceinline__ unsigned fkey(float f) {
    unsigned b = __float_as_uint(f);
    return (b & 0x80000000u) ? ~b : (b | 0x80000000u);
}
__device__ __forceinline__ float funkey(unsigned u) {
    unsigned b = (u & 0x80000000u) ? (u & 0x7FFFFFFFu) : ~u;
    return __uint_as_float(b);
}

// ---------------------------------------------------------------------------
// Kernel A: box-masked pooling sums. UNCHANGED math from R14 (proven best).
// Also resets g_maxbits deterministically each launch (runs first in stream).
// ---------------------------------------------------------------------------
__global__ void __launch_bounds__(DPB) proto_kernel(const float* __restrict__ patches,
                                                    const float* __restrict__ annos) {
    int b = blockIdx.x, t = blockIdx.y;
    int d = blockIdx.z * DPB + threadIdx.x;

    if (t == 0 && blockIdx.z == 0 && threadIdx.x == 0) g_maxbits[b] = 0u;

    const float* a = annos + (t * B_ + b) * 4;
    float a0 = a[0], a1 = a[1], a2 = a[2], a3 = a[3];
    int x1 = (int)floorf(a0 * (float)WT);
    int y1 = (int)floorf(a1 * (float)HT);
    int x2 = (int)floorf((a0 + a2) * (float)WT);
    int y2 = (int)floorf((a1 + a3) * (float)HT);

    const float* base = patches + ((size_t)(t * B_ + b)) * NT * D_ + d;
    float s = 0.f;
    int c = 0;
#pragma unroll
    for (int r = 0; r < HT; r++) {
        bool inr = (r >= y1) && (r < y2);
#pragma unroll
        for (int cc = 0; cc < WT; cc++) {
            bool in = inr && (cc >= x1) && (cc < x2);
            float m = in ? 1.0f : 0.0f;
            c += in ? 1 : 0;
            s += m * base[(size_t)(r * WT + cc) * D_];
        }
    }
    g_acc[t][b][d] = s;
    if (blockIdx.z == 0 && threadIdx.x == 0) g_cnt[t][b] = (float)c;
}

// ---------------------------------------------------------------------------
// Kernel B: attn + head-mean -> track. UNCHANGED from R14 (proven best).
// ---------------------------------------------------------------------------
__global__ void __launch_bounds__(32*AWRP) attn_kernel(const float* __restrict__ skey) {
    int b    = blockIdx.y;
    int warp = threadIdx.x >> 5;
    int lane = threadIdx.x & 31;
    int hl   = lane >> 4;     // 0 or 1
    int d4   = lane & 15;     // float4 index within head

    float c0 = g_cnt[0][b] + 1e-6f;
    float c1 = g_cnt[1][b] + 1e-6f;

    float4 pr[6];
#pragma unroll
    for (int j = 0; j < 6; j++) {
        int h = 2 * j + hl;
        float4 q0 = *(const float4*)(&g_acc[0][b][h * HD + d4 * 4]);
        float4 q1 = *(const float4*)(&g_acc[1][b][h * HD + d4 * 4]);
        pr[j].x = 0.5f * (q0.x / c0 + q1.x / c1);
        pr[j].y = 0.5f * (q0.y / c0 + q1.y / c1);
        pr[j].z = 0.5f * (q0.z / c0 + q1.z / c1);
        pr[j].w = 0.5f * (q0.w / c0 + q1.w / c1);
    }

    int n0 = blockIdx.x * (AWRP * NPW) + warp * NPW;
    const float* kb = skey + ((size_t)b * HEADS) * (size_t)NK * HD;

    float acc[NPW];
#pragma unroll
    for (int r = 0; r < NPW; r++) acc[r] = 0.f;

#pragma unroll
    for (int j = 0; j < 6; j++) {
        int h = 2 * j + hl;
        const float4* p = (const float4*)(kb + ((size_t)h * NK + (size_t)(n0 + 1)) * HD) + d4;
#pragma unroll
        for (int r = 0; r < NPW; r++) {
            float4 k = __ldcs(p + r * (HD / 4));
            acc[r] += k.x * pr[j].x + k.y * pr[j].y + k.z * pr[j].z + k.w * pr[j].w;
        }
    }

    const float scale = 0.125f / 12.0f;   // hd^-0.5 / heads
#pragma unroll
    for (int r = 0; r < NPW; r++) {
#pragma unroll
        for (int off = 16; off; off >>= 1)
            acc[r] += __shfl_xor_sync(0xffffffffu, acc[r], off);
    }
    if (lane == 0) {
        float4* tr = (float4*)(g_track + b * NS + n0);
#pragma unroll
        for (int q = 0; q < NPW / 4; q++) {
            tr[q] = make_float4(acc[4 * q + 0] * scale, acc[4 * q + 1] * scale,
                                acc[4 * q + 2] * scale, acc[4 * q + 3] * scale);
        }
    }
}

// ---------------------------------------------------------------------------
// Kernel BL: fully-parallel blur (closed form, bit-identical) + per-batch
// max accumulation (max is order-insensitive -> atomicMax on uint key).
// ---------------------------------------------------------------------------
__device__ __forceinline__ int reflect_idx(int i, int n) {
    if (i < 0)  return -i;
    if (i >= n) return 2 * n - 2 - i;
    return i;
}

__device__ __forceinline__ float vblur_at(const float* __restrict__ tr, int y, int x,
                                          float w0, float w1, float w2) {
    float vm2 = tr[reflect_idx(y - 2, HS) * WS + x];
    float vm1 = tr[reflect_idx(y - 1, HS) * WS + x];
    float v0  = tr[y * WS + x];
    float vp1 = tr[reflect_idx(y + 1, HS) * WS + x];
    float vp2 = tr[reflect_idx(y + 2, HS) * WS + x];
    return w2 * vm2 + w1 * vm1 + w0 * v0 + w1 * vp1 + w2 * vp2;
}

__global__ void __launch_bounds__(256) blur_kernel() {
    __shared__ float smax[8];
    int b = blockIdx.y;
    int i = blockIdx.x * 256 + threadIdx.x;
    int y = i / WS, x = i - y * WS;
    int lane = threadIdx.x & 31, wid = threadIdx.x >> 5;

    float k1 = expf(-1.0f / 2.42f);
    float k2 = expf(-4.0f / 2.42f);
    float s  = 1.0f + 2.0f * k1 + 2.0f * k2;
    float w0 = 1.0f / s, w1 = k1 / s, w2 = k2 / s;

    const float* tr = g_track + b * NS;
    float vm2 = vblur_at(tr, y, reflect_idx(x - 2, WS), w0, w1, w2);
    float vm1 = vblur_at(tr, y, reflect_idx(x - 1, WS), w0, w1, w2);
    float v0  = vblur_at(tr, y, x,                      w0, w1, w2);
    float vp1 = vblur_at(tr, y, reflect_idx(x + 1, WS), w0, w1, w2);
    float vp2 = vblur_at(tr, y, reflect_idx(x + 2, WS), w0, w1, w2);
    float v = w2 * vm2 + w1 * vm1 + w0 * v0 + w1 * vp1 + w2 * vp2;
    g_blurh[b * NS + i] = v;

    // block max (order-insensitive, exact) -> atomicMax on key
    float mv = v;
#pragma unroll
    for (int o = 16; o; o >>= 1) mv = fmaxf(mv, __shfl_xor_sync(0xffffffffu, mv, o));
    if (lane == 0) smax[wid] = mv;
    __syncthreads();
    if (threadIdx.x == 0) {
        float bm = smax[0];
#pragma unroll
        for (int q = 1; q < 8; q++) bm = fmaxf(bm, smax[q]);
        atomicMax(&g_maxbits[b], fkey(bm));
    }
}

// ---------------------------------------------------------------------------
// Kernel E: elementwise exp(blur - max), full chip. Bit-exact per element.
// ---------------------------------------------------------------------------
__global__ void __launch_bounds__(256) exp_kernel() {
    int b = blockIdx.y;
    int i = blockIdx.x * 256 + threadIdx.x;
    float m = funkey(g_maxbits[b]);
    g_exp[b * NS + i] = expf(g_blurh[b * NS + i] - m);
}

// ---------------------------------------------------------------------------
// Kernel C: per-batch post starting at the sum. Sum uses the EXACT strided
// order + 256-tree of the passing kernel (inputs bit-identical), then prob
// write, integral image, window argmax — all unchanged.
// ---------------------------------------------------------------------------
__global__ void __launch_bounds__(256) post_kernel(float* __restrict__ out) {
    __shared__ float sA[NS];
    __shared__ float red[256];
    __shared__ int   redi[256];

    int b   = blockIdx.x;
    int tid = threadIdx.x;

    // load exp values + sum in the exact previous order
    const float* ge = g_exp + b * NS;
    float sum = 0.f;
    for (int i = tid; i < NS; i += 256) { float e = ge[i]; sA[i] = e; sum += e; }
    red[tid] = sum; __syncthreads();
    for (int off = 128; off; off >>= 1) {
        if (tid < off) red[tid] += red[tid + off];
        __syncthreads();
    }
    float inv = 1.0f / red[0]; __syncthreads();

    // prob normalize + write (elementwise, vectorized)
    float4* dst4 = (float4*)sA;
    float4* probOut4 = (float4*)(out + 5 * B_ + (size_t)b * NS);
    for (int i = tid; i < NS / 4; i += 256) {
        float4 e = dst4[i];
        float4 p = make_float4(e.x * inv, e.y * inv, e.z * inv, e.w * inv);
        dst4[i] = p;
        probOut4[i] = p;
    }
    __syncthreads();

    // integral image: row cumsum then column cumsum (matches jnp order)
    if (tid < HS) {
        float c = 0.f;
        float* r = sA + tid * WS;
        for (int x = 0; x < WS; x++) { c += r[x]; r[x] = c; }
    }
    __syncthreads();
    if (tid < WS) {
        float c = 0.f;
        for (int y = 0; y < HS; y++) { c += sA[y * WS + tid]; sA[y * WS + tid] = c; }
    }
    __syncthreads();

    // 14x14 window sums over 83x83 positions, first-occurrence argmax
    float bv = -3.402823e38f;
    int   bi = 0x7fffffff;
    for (int i = tid; i < SMH * SMW; i += 256) {
        int y = i / SMW, x = i - y * SMW;
        float Dv = sA[(y + HT - 1) * WS + (x + WT - 1)];
        float Bv = (y > 0)          ? sA[(y - 1) * WS + (x + WT - 1)] : 0.0f;
        float Cv = (x > 0)          ? sA[(y + HT - 1) * WS + (x - 1)] : 0.0f;
        float Av = (y > 0 && x > 0) ? sA[(y - 1) * WS + (x - 1)]      : 0.0f;
        float v = Dv - Bv - Cv + Av;
        if (v > bv || (v == bv && i < bi)) { bv = v; bi = i; }
    }
    red[tid] = bv; redi[tid] = bi; __syncthreads();
    for (int off = 128; off; off >>= 1) {
        if (tid < off) {
            float ov = red[tid + off]; int oi = redi[tid + off];
            if (ov > red[tid] || (ov == red[tid] && oi < redi[tid])) {
                red[tid] = ov; redi[tid] = oi;
            }
        }
        __syncthreads();
    }
    if (tid == 0) {
        int idx = redi[0];
        out[0 * B_ + b] = (float)(idx % SMW);   // best_x
        out[1 * B_ + b] = (float)(idx / SMW);   // best_y
        out[2 * B_ + b] = (float)WT;            // win_w
        out[3 * B_ + b] = (float)HT;            // win_h
        out[4 * B_ + b] = red[0];               // confidence
    }
}

// ---------------------------------------------------------------------------
extern "C" void kernel_launch(void* const* d_in, const int* in_sizes, int n_in,
                              void* d_out, int out_size) {
    const float* patches = (const float*)d_in[0];
    const float* annos   = (const float*)d_in[1];
    const float* skey    = (const float*)d_in[2];
    float* out = (float*)d_out;

    proto_kernel<<<dim3(B_, T_, DCH), DPB>>>(patches, annos);

    dim3 gAttn(NS / (AWRP * NPW), B_);   // 144 x 32
    attn_kernel<<<gAttn, 32 * AWRP>>>(skey);

    dim3 gMap(NS / 256, B_);             // 36 x 32
    blur_kernel<<<gMap, 256>>>();
    exp_kernel<<<gMap, 256>>>();

    post_kernel<<<B_, 256>>>(out);
}

// round 17
// speedup vs baseline: 1.0347x; 1.0347x over previous
#include <cuda_runtime.h>
#include <math.h>

#define B_    32
#define T_    2
#define NT    196
#define D_    768
#define HEADS 12
#define HD    64
#define HT    14
#define WT    14
#define HS    96
#define WS    96
#define NS    (HS*WS)       // 9216
#define NK    (NS+1)        // 9217
#define SMH   (HS-HT+1)     // 83
#define SMW   (WS-WT+1)     // 83
#define NPW   16            // n-values per warp in attn
#define AWRP  4             // warps per attn block
#define DCH   8             // dim-chunks in proto grid
#define DPB   (D_/DCH)      // 96 threads per proto block
#define PTH   1024          // post threads

__device__ float    g_acc[T_][B_][D_];  // per-template masked sums (pre-division)
__device__ float    g_cnt[T_][B_];      // per-template counts
__device__ float    g_track[B_*NS];
__device__ float    g_blurh[B_*NS];     // fully blurred map
__device__ unsigned g_maxbits[B_];      // per-batch max as monotonic uint key

// float <-> monotonic unsigned key (exact; max over keys == max over floats)
__device__ __forceinline__ unsigned fkey(float f) {
    unsigned b = __float_as_uint(f);
    return (b & 0x80000000u) ? ~b : (b | 0x80000000u);
}
__device__ __forceinline__ float funkey(unsigned u) {
    unsigned b = (u & 0x80000000u) ? (u & 0x7FFFFFFFu) : ~u;
    return __uint_as_float(b);
}

// ---------------------------------------------------------------------------
// Kernel A: box-masked pooling sums. UNCHANGED math (proven best).
// Resets g_maxbits deterministically each launch (runs first in stream).
// ---------------------------------------------------------------------------
__global__ void __launch_bounds__(DPB) proto_kernel(const float* __restrict__ patches,
                                                    const float* __restrict__ annos) {
    int b = blockIdx.x, t = blockIdx.y;
    int d = blockIdx.z * DPB + threadIdx.x;

    if (t == 0 && blockIdx.z == 0 && threadIdx.x == 0) g_maxbits[b] = 0u;

    const float* a = annos + (t * B_ + b) * 4;
    float a0 = a[0], a1 = a[1], a2 = a[2], a3 = a[3];
    int x1 = (int)floorf(a0 * (float)WT);
    int y1 = (int)floorf(a1 * (float)HT);
    int x2 = (int)floorf((a0 + a2) * (float)WT);
    int y2 = (int)floorf((a1 + a3) * (float)HT);

    const float* base = patches + ((size_t)(t * B_ + b)) * NT * D_ + d;
    float s = 0.f;
    int c = 0;
#pragma unroll
    for (int r = 0; r < HT; r++) {
        bool inr = (r >= y1) && (r < y2);
#pragma unroll
        for (int cc = 0; cc < WT; cc++) {
            bool in = inr && (cc >= x1) && (cc < x2);
            float m = in ? 1.0f : 0.0f;
            c += in ? 1 : 0;
            s += m * base[(size_t)(r * WT + cc) * D_];
        }
    }
    g_acc[t][b][d] = s;
    if (blockIdx.z == 0 && threadIdx.x == 0) g_cnt[t][b] = (float)c;
}

// ---------------------------------------------------------------------------
// Kernel B: attn + head-mean -> track. UNCHANGED from R14 (proven best).
// ---------------------------------------------------------------------------
__global__ void __launch_bounds__(32*AWRP) attn_kernel(const float* __restrict__ skey) {
    int b    = blockIdx.y;
    int warp = threadIdx.x >> 5;
    int lane = threadIdx.x & 31;
    int hl   = lane >> 4;     // 0 or 1
    int d4   = lane & 15;     // float4 index within head

    float c0 = g_cnt[0][b] + 1e-6f;
    float c1 = g_cnt[1][b] + 1e-6f;

    float4 pr[6];
#pragma unroll
    for (int j = 0; j < 6; j++) {
        int h = 2 * j + hl;
        float4 q0 = *(const float4*)(&g_acc[0][b][h * HD + d4 * 4]);
        float4 q1 = *(const float4*)(&g_acc[1][b][h * HD + d4 * 4]);
        pr[j].x = 0.5f * (q0.x / c0 + q1.x / c1);
        pr[j].y = 0.5f * (q0.y / c0 + q1.y / c1);
        pr[j].z = 0.5f * (q0.z / c0 + q1.z / c1);
        pr[j].w = 0.5f * (q0.w / c0 + q1.w / c1);
    }

    int n0 = blockIdx.x * (AWRP * NPW) + warp * NPW;
    const float* kb = skey + ((size_t)b * HEADS) * (size_t)NK * HD;

    float acc[NPW];
#pragma unroll
    for (int r = 0; r < NPW; r++) acc[r] = 0.f;

#pragma unroll
    for (int j = 0; j < 6; j++) {
        int h = 2 * j + hl;
        const float4* p = (const float4*)(kb + ((size_t)h * NK + (size_t)(n0 + 1)) * HD) + d4;
#pragma unroll
        for (int r = 0; r < NPW; r++) {
            float4 k = __ldcs(p + r * (HD / 4));
            acc[r] += k.x * pr[j].x + k.y * pr[j].y + k.z * pr[j].z + k.w * pr[j].w;
        }
    }

    const float scale = 0.125f / 12.0f;   // hd^-0.5 / heads
#pragma unroll
    for (int r = 0; r < NPW; r++) {
#pragma unroll
        for (int off = 16; off; off >>= 1)
            acc[r] += __shfl_xor_sync(0xffffffffu, acc[r], off);
    }
    if (lane == 0) {
        float4* tr = (float4*)(g_track + b * NS + n0);
#pragma unroll
        for (int q = 0; q < NPW / 4; q++) {
            tr[q] = make_float4(acc[4 * q + 0] * scale, acc[4 * q + 1] * scale,
                                acc[4 * q + 2] * scale, acc[4 * q + 3] * scale);
        }
    }
}

// ---------------------------------------------------------------------------
// Kernel BL: fully-parallel blur (closed form, bit-identical) + per-batch
// max via atomicMax on uint key (validated bit-exact in R16).
// ---------------------------------------------------------------------------
__device__ __forceinline__ int reflect_idx(int i, int n) {
    if (i < 0)  return -i;
    if (i >= n) return 2 * n - 2 - i;
    return i;
}

__device__ __forceinline__ float vblur_at(const float* __restrict__ tr, int y, int x,
                                          float w0, float w1, float w2) {
    float vm2 = tr[reflect_idx(y - 2, HS) * WS + x];
    float vm1 = tr[reflect_idx(y - 1, HS) * WS + x];
    float v0  = tr[y * WS + x];
    float vp1 = tr[reflect_idx(y + 1, HS) * WS + x];
    float vp2 = tr[reflect_idx(y + 2, HS) * WS + x];
    return w2 * vm2 + w1 * vm1 + w0 * v0 + w1 * vp1 + w2 * vp2;
}

__global__ void __launch_bounds__(256) blur_kernel() {
    __shared__ float smax[8];
    int b = blockIdx.y;
    int i = blockIdx.x * 256 + threadIdx.x;
    int y = i / WS, x = i - y * WS;
    int lane = threadIdx.x & 31, wid = threadIdx.x >> 5;

    float k1 = expf(-1.0f / 2.42f);
    float k2 = expf(-4.0f / 2.42f);
    float s  = 1.0f + 2.0f * k1 + 2.0f * k2;
    float w0 = 1.0f / s, w1 = k1 / s, w2 = k2 / s;

    const float* tr = g_track + b * NS;
    float vm2 = vblur_at(tr, y, reflect_idx(x - 2, WS), w0, w1, w2);
    float vm1 = vblur_at(tr, y, reflect_idx(x - 1, WS), w0, w1, w2);
    float v0  = vblur_at(tr, y, x,                      w0, w1, w2);
    float vp1 = vblur_at(tr, y, reflect_idx(x + 1, WS), w0, w1, w2);
    float vp2 = vblur_at(tr, y, reflect_idx(x + 2, WS), w0, w1, w2);
    float v = w2 * vm2 + w1 * vm1 + w0 * v0 + w1 * vp1 + w2 * vp2;
    g_blurh[b * NS + i] = v;

    float mv = v;
#pragma unroll
    for (int o = 16; o; o >>= 1) mv = fmaxf(mv, __shfl_xor_sync(0xffffffffu, mv, o));
    if (lane == 0) smax[wid] = mv;
    __syncthreads();
    if (threadIdx.x == 0) {
        float bm = smax[0];
#pragma unroll
        for (int q = 1; q < 8; q++) bm = fmaxf(bm, smax[q]);
        atomicMax(&g_maxbits[b], fkey(bm));
    }
}

// ---------------------------------------------------------------------------
// Kernel C: 1024-thread post. Bit-exactness per phase:
//  - exp: elementwise (any thread may compute any element)
//  - SUM: threads 0-255 only, exact R15 strided order + 256-tree
//  - prob: elementwise
//  - cumsums: tid<96 serial (unchanged)
//  - argmax: exact comparisons -> partition-independent result
// ---------------------------------------------------------------------------
__global__ void __launch_bounds__(PTH) post_kernel(float* __restrict__ out) {
    __shared__ float sA[NS];
    __shared__ float red[256];
    __shared__ float redm[32];
    __shared__ int   redmi[32];

    int b    = blockIdx.x;
    int tid  = threadIdx.x;
    int lane = tid & 31;
    int wid  = tid >> 5;

    float m = funkey(g_maxbits[b]);

    // exp phase: 1024 threads, elementwise (bit-identical values)
    const float* gb = g_blurh + b * NS;
#pragma unroll
    for (int it = 0; it < NS / PTH; it++) {
        int i = tid + it * PTH;
        sA[i] = expf(gb[i] - m);
    }
    __syncthreads();

    // SUM: threads 0-255 reproduce the exact prior strided order + tree
    if (tid < 256) {
        float sum = 0.f;
        for (int i = tid; i < NS; i += 256) sum += sA[i];
        red[tid] = sum;
    }
    __syncthreads();
    for (int off = 128; off; off >>= 1) {
        if (tid < off) red[tid] += red[tid + off];
        __syncthreads();
    }
    float inv = 1.0f / red[0];
    __syncthreads();

    // prob normalize + write (elementwise, vectorized)
    float4* dst4 = (float4*)sA;
    float4* probOut4 = (float4*)(out + 5 * B_ + (size_t)b * NS);
#pragma unroll
    for (int it = 0; it < NS / 4 / PTH + 1; it++) {
        int i = tid + it * PTH;
        if (i < NS / 4) {
            float4 e = dst4[i];
            float4 p = make_float4(e.x * inv, e.y * inv, e.z * inv, e.w * inv);
            dst4[i] = p;
            probOut4[i] = p;
        }
    }
    __syncthreads();

    // integral image: row cumsum then column cumsum (matches jnp order)
    if (tid < HS) {
        float c = 0.f;
        float* r = sA + tid * WS;
        for (int x = 0; x < WS; x++) { c += r[x]; r[x] = c; }
    }
    __syncthreads();
    if (tid < WS) {
        float c = 0.f;
        for (int y = 0; y < HS; y++) { c += sA[y * WS + tid]; sA[y * WS + tid] = c; }
    }
    __syncthreads();

    // 14x14 window argmax: exact compares -> same result for any partition
    float bv = -3.402823e38f;
    int   bi = 0x7fffffff;
    for (int i = tid; i < SMH * SMW; i += PTH) {
        int y = i / SMW, x = i - y * SMW;
        float Dv = sA[(y + HT - 1) * WS + (x + WT - 1)];
        float Bv = (y > 0)          ? sA[(y - 1) * WS + (x + WT - 1)] : 0.0f;
        float Cv = (x > 0)          ? sA[(y + HT - 1) * WS + (x - 1)] : 0.0f;
        float Av = (y > 0 && x > 0) ? sA[(y - 1) * WS + (x - 1)]      : 0.0f;
        float v = Dv - Bv - Cv + Av;
        if (v > bv || (v == bv && i < bi)) { bv = v; bi = i; }
    }
#pragma unroll
    for (int o = 16; o; o >>= 1) {
        float ov = __shfl_xor_sync(0xffffffffu, bv, o);
        int   oi = __shfl_xor_sync(0xffffffffu, bi, o);
        if (ov > bv || (ov == bv && oi < bi)) { bv = ov; bi = oi; }
    }
    if (lane == 0) { redm[wid] = bv; redmi[wid] = bi; }
    __syncthreads();
    if (wid == 0) {
        float v = redm[lane];
        int   i = redmi[lane];
#pragma unroll
        for (int o = 16; o; o >>= 1) {
            float ov = __shfl_xor_sync(0xffffffffu, v, o);
            int   oi = __shfl_xor_sync(0xffffffffu, i, o);
            if (ov > v || (ov == v && oi < i)) { v = ov; i = oi; }
        }
        if (lane == 0) {
            out[0 * B_ + b] = (float)(i % SMW);   // best_x
            out[1 * B_ + b] = (float)(i / SMW);   // best_y
            out[2 * B_ + b] = (float)WT;          // win_w
            out[3 * B_ + b] = (float)HT;          // win_h
            out[4 * B_ + b] = v;                  // confidence
        }
    }
}

// ---------------------------------------------------------------------------
extern "C" void kernel_launch(void* const* d_in, const int* in_sizes, int n_in,
                              void* d_out, int out_size) {
    const float* patches = (const float*)d_in[0];
    const float* annos   = (const float*)d_in[1];
    const float* skey    = (const float*)d_in[2];
    float* out = (float*)d_out;

    proto_kernel<<<dim3(B_, T_, DCH), DPB>>>(patches, annos);

    dim3 gAttn(NS / (AWRP * NPW), B_);   // 144 x 32
    attn_kernel<<<gAttn, 32 * AWRP>>>(skey);

    dim3 gMap(NS / 256, B_);             // 36 x 32
    blur_kernel<<<gMap, 256>>>();

    post_kernel<<<B_, PTH>>>(out);
}